// round 15
// baseline (speedup 1.0000x reference)
#include <cuda_runtime.h>

#define TH 16
#define TW 64
#define NTILE 2
#define NT 256
#define HIMG 512
#define WIMG 512
#define SAW 68   // padded row stride for s_a
#define SCW 36   // padded row stride for s_c (half-res chroma)

__constant__ float c_D[64];   // DCT matrix, row-major

__global__ __launch_bounds__(NT, 5) void jpeg_kernel(
    const float* __restrict__ in, const float* __restrict__ quant,
    const float* __restrict__ dct, float* __restrict__ out)
{
    __shared__ __align__(16) float s_a[3][TH][SAW];   // y / A' / V / Z
    __shared__ __align__(16) float s_c[2][TH/2][SCW]; // half-res chroma
    __shared__ __align__(16) float s_d[8][8];         // D (lane-varying reads)
    __shared__ __align__(16) float s_dt[8][8];        // D^T
    __shared__ __align__(16) float s_e[8][4];         // E
    __shared__ __align__(16) float s_q[3][8][8];
    __shared__ __align__(16) float s_rq[3][8][8];

    const int tid = threadIdx.x;
    const int b   = blockIdx.z;
    const int ty0 = blockIdx.y * TH;
    const int tx00 = blockIdx.x * (TW * NTILE);

    const size_t plane = (size_t)HIMG * WIMG;
    const float* base  = in  + (size_t)b * 3 * plane;
    float*       obase = out + (size_t)b * 3 * plane;

    // ---- per-thread pixel coords (same every tile; tile adds tx offset) ----
    const int sy = tid >> 4;                 // 0..15 (row)
    const int sx = tid & 15;                 // 0..15 (strip)
    const int px = sx * 4;

    // ---- tile-0 global loads issued FIRST (overlap table setup with DRAM) ----
    size_t gidx = (size_t)(ty0 + sy) * WIMG + (tx00 + px);
    float4 r4 = __ldg((const float4*)&base[gidx]);
    float4 g4 = __ldg((const float4*)&base[plane + gidx]);
    float4 b4 = __ldg((const float4*)&base[2*plane + gidx]);

    // ---- tables (overlapped with load latency; once per CTA = 2 tiles) ----
    if (tid < 64) {
        float v = dct[tid];
        int i = tid >> 3, j = tid & 7;
        s_d[i][j]  = v;
        s_dt[j][i] = v;
    }
    if (tid < 32) {
        int i = tid >> 2, h = tid & 3;
        s_e[i][h] = dct[i * 8 + 2 * h] + dct[i * 8 + 2 * h + 1];
    }
    if (tid >= 64) {
        int i = tid - 64;
        float qv = rintf(quant[i] * 255.0f);
        float q1 = rintf((qv * 50.0f + 50.0f) / 100.0f);
        float q  = fminf(fmaxf(q1, 1.0f), 255.0f);
        int ci = i >> 6, ri = (i >> 3) & 7, li = i & 7;
        s_q[ci][ri][li]  = q;
        s_rq[ci][ri][li] = 1.0f / q;
    }

    // ---- DCT-section assignment (tile-invariant) ----
    const bool act = tid < 192;
    const int unit = tid >> 2;    // 0..47
    const int r    = tid & 3;
    int c, by, bx;
    if (unit < 16) { c = 0; by = unit >> 3; bx = unit & 7; }
    else { int t = unit - 16; c = 1 + (t >> 4); int rem = t & 15; by = rem >> 3; bx = rem & 7; }
    const int ra = r, rb = r + 4;
    float* pW = &s_a[c][by*8][bx*8];

    #pragma unroll
    for (int tile = 0; tile < NTILE; tile++) {
        const int tx0 = tx00 + tile * TW;
        if (tile > 0) {
            __syncthreads();   // prior phase-5 reads of s_a complete
            gidx = (size_t)(ty0 + sy) * WIMG + (tx0 + px);
            r4 = __ldg((const float4*)&base[gidx]);
            g4 = __ldg((const float4*)&base[plane + gidx]);
            b4 = __ldg((const float4*)&base[2*plane + gidx]);
        }

        // ---- phase 1: color transform; chroma 2x2 mean via in-warp shuffle ----
        {
            float R[4] = {255.0f*r4.x, 255.0f*r4.y, 255.0f*r4.z, 255.0f*r4.w};
            float G[4] = {255.0f*g4.x, 255.0f*g4.y, 255.0f*g4.z, 255.0f*g4.w};
            float B[4] = {255.0f*b4.x, 255.0f*b4.y, 255.0f*b4.z, 255.0f*b4.w};

            #define YV(R_,G_,B_)  fmaf(0.114f,(B_), fmaf(0.587f,(G_), 0.299f*(R_)))
            #define CBV(R_,G_,B_) (fmaf(0.5f,(B_),  fmaf(-0.331264108f,(G_), -0.168735892f*(R_))) + 128.0f)
            #define CRV(R_,G_,B_) (fmaf(-0.081312411f,(B_), fmaf(-0.418687589f,(G_), 0.5f*(R_))) + 128.0f)
            #define CL(v) fminf(fmaxf((v), 0.0f), 255.0f)

            float Y[4], CB[4], CR[4];
            #pragma unroll
            for (int e = 0; e < 4; e++) {
                Y[e]  = CL(YV(R[e], G[e], B[e])) - 128.0f;
                CB[e] = CL(CBV(R[e], G[e], B[e]));
                CR[e] = CL(CRV(R[e], G[e], B[e]));
            }
            *(float4*)&s_a[0][sy][px] = make_float4(Y[0], Y[1], Y[2], Y[3]);

            float pcb0 = __shfl_xor_sync(0xffffffffu, CB[0], 16);
            float pcb1 = __shfl_xor_sync(0xffffffffu, CB[1], 16);
            float pcb2 = __shfl_xor_sync(0xffffffffu, CB[2], 16);
            float pcb3 = __shfl_xor_sync(0xffffffffu, CB[3], 16);
            float pcr0 = __shfl_xor_sync(0xffffffffu, CR[0], 16);
            float pcr1 = __shfl_xor_sync(0xffffffffu, CR[1], 16);
            float pcr2 = __shfl_xor_sync(0xffffffffu, CR[2], 16);
            float pcr3 = __shfl_xor_sync(0xffffffffu, CR[3], 16);
            if ((sy & 1) == 0) {
                float cbm0 = 0.25f * (((CB[0] + CB[1]) + pcb0) + pcb1) - 128.0f;
                float cbm1 = 0.25f * (((CB[2] + CB[3]) + pcb2) + pcb3) - 128.0f;
                float crm0 = 0.25f * (((CR[0] + CR[1]) + pcr0) + pcr1) - 128.0f;
                float crm1 = 0.25f * (((CR[2] + CR[3]) + pcr2) + pcr3) - 128.0f;
                *(float2*)&s_c[0][sy >> 1][sx*2] = make_float2(cbm0, cbm1);
                *(float2*)&s_c[1][sy >> 1][sx*2] = make_float2(crm0, crm1);
            }
        }
        __syncthreads();

        if (act) {
            // ---- stage 1: A' = X * D^T (row-local; uniform const coeffs) ----
            if (c == 0) {
                #pragma unroll
                for (int pass = 0; pass < 2; pass++) {
                    const int rr = pass ? rb : ra;
                    const float4 x0 = *(const float4*)(pW + rr*SAW);
                    const float4 x1 = *(const float4*)(pW + rr*SAW + 4);
                    float A[8];
                    #pragma unroll
                    for (int l = 0; l < 8; l++) {
                        const float4 d0 = *(const float4*)&c_D[l*8];
                        const float4 d1 = *(const float4*)&c_D[l*8 + 4];
                        A[l] = fmaf(x1.w, d1.w, fmaf(x1.z, d1.z, fmaf(x1.y, d1.y,
                               fmaf(x1.x, d1.x, fmaf(x0.w, d0.w, fmaf(x0.z, d0.z,
                               fmaf(x0.y, d0.y, x0.x * d0.x)))))));
                    }
                    *(float4*)(pW + rr*SAW)     = make_float4(A[0], A[1], A[2], A[3]);
                    *(float4*)(pW + rr*SAW + 4) = make_float4(A[4], A[5], A[6], A[7]);
                }
            } else {
                const float* pC = &s_c[c-1][by*4][bx*4];
                const float4 xh = *(const float4*)(pC + r*SCW);
                float A[8];
                #pragma unroll
                for (int l = 0; l < 8; l++) {
                    const float4 d0 = *(const float4*)&c_D[l*8];
                    const float4 d1 = *(const float4*)&c_D[l*8 + 4];
                    float e0 = d0.x + d0.y, e1 = d0.z + d0.w;
                    float e2 = d1.x + d1.y, e3 = d1.z + d1.w;
                    A[l] = fmaf(xh.w, e3, fmaf(xh.z, e2, fmaf(xh.y, e1, xh.x * e0)));
                }
                *(float4*)(pW + r*SAW)     = make_float4(A[0], A[1], A[2], A[3]);
                *(float4*)(pW + r*SAW + 4) = make_float4(A[4], A[5], A[6], A[7]);
            }
            __syncwarp();   // unit (4 threads) is warp-local: A' visible

            // ---- stage 2: F = D * A' (transpose), quant/dequant, V = dec * D ----
            float Va[8], Vb[8];
            {
                float Fa[8], Fb[8];
                #pragma unroll
                for (int l = 0; l < 8; l++) { Fa[l] = 0.0f; Fb[l] = 0.0f; }
                if (c == 0) {
                    #pragma unroll
                    for (int j = 0; j < 8; j++) {
                        const float da = s_d[ra][j];
                        const float db = s_d[rb][j];
                        const float4 a0 = *(const float4*)(pW + j*SAW);
                        const float4 a1 = *(const float4*)(pW + j*SAW + 4);
                        Fa[0] = fmaf(da, a0.x, Fa[0]);  Fb[0] = fmaf(db, a0.x, Fb[0]);
                        Fa[1] = fmaf(da, a0.y, Fa[1]);  Fb[1] = fmaf(db, a0.y, Fb[1]);
                        Fa[2] = fmaf(da, a0.z, Fa[2]);  Fb[2] = fmaf(db, a0.z, Fb[2]);
                        Fa[3] = fmaf(da, a0.w, Fa[3]);  Fb[3] = fmaf(db, a0.w, Fb[3]);
                        Fa[4] = fmaf(da, a1.x, Fa[4]);  Fb[4] = fmaf(db, a1.x, Fb[4]);
                        Fa[5] = fmaf(da, a1.y, Fa[5]);  Fb[5] = fmaf(db, a1.y, Fb[5]);
                        Fa[6] = fmaf(da, a1.z, Fa[6]);  Fb[6] = fmaf(db, a1.z, Fb[6]);
                        Fa[7] = fmaf(da, a1.w, Fa[7]);  Fb[7] = fmaf(db, a1.w, Fb[7]);
                    }
                } else {
                    #pragma unroll
                    for (int m = 0; m < 4; m++) {
                        const float ea = s_e[ra][m];
                        const float eb = s_e[rb][m];
                        const float4 a0 = *(const float4*)(pW + m*SAW);
                        const float4 a1 = *(const float4*)(pW + m*SAW + 4);
                        Fa[0] = fmaf(ea, a0.x, Fa[0]);  Fb[0] = fmaf(eb, a0.x, Fb[0]);
                        Fa[1] = fmaf(ea, a0.y, Fa[1]);  Fb[1] = fmaf(eb, a0.y, Fb[1]);
                        Fa[2] = fmaf(ea, a0.z, Fa[2]);  Fb[2] = fmaf(eb, a0.z, Fb[2]);
                        Fa[3] = fmaf(ea, a0.w, Fa[3]);  Fb[3] = fmaf(eb, a0.w, Fb[3]);
                        Fa[4] = fmaf(ea, a1.x, Fa[4]);  Fb[4] = fmaf(eb, a1.x, Fb[4]);
                        Fa[5] = fmaf(ea, a1.y, Fa[5]);  Fb[5] = fmaf(eb, a1.y, Fb[5]);
                        Fa[6] = fmaf(ea, a1.z, Fa[6]);  Fb[6] = fmaf(eb, a1.z, Fb[6]);
                        Fa[7] = fmaf(ea, a1.w, Fa[7]);  Fb[7] = fmaf(eb, a1.w, Fb[7]);
                    }
                }
                {
                    const float4 q0  = *(const float4*)&s_q[c][ra][0];
                    const float4 q1  = *(const float4*)&s_q[c][ra][4];
                    const float4 rq0 = *(const float4*)&s_rq[c][ra][0];
                    const float4 rq1 = *(const float4*)&s_rq[c][ra][4];
                    Fa[0] = rintf(rintf(Fa[0]*rq0.x)*q0.x);  Fa[1] = rintf(rintf(Fa[1]*rq0.y)*q0.y);
                    Fa[2] = rintf(rintf(Fa[2]*rq0.z)*q0.z);  Fa[3] = rintf(rintf(Fa[3]*rq0.w)*q0.w);
                    Fa[4] = rintf(rintf(Fa[4]*rq1.x)*q1.x);  Fa[5] = rintf(rintf(Fa[5]*rq1.y)*q1.y);
                    Fa[6] = rintf(rintf(Fa[6]*rq1.z)*q1.z);  Fa[7] = rintf(rintf(Fa[7]*rq1.w)*q1.w);
                }
                {
                    const float4 q0  = *(const float4*)&s_q[c][rb][0];
                    const float4 q1  = *(const float4*)&s_q[c][rb][4];
                    const float4 rq0 = *(const float4*)&s_rq[c][rb][0];
                    const float4 rq1 = *(const float4*)&s_rq[c][rb][4];
                    Fb[0] = rintf(rintf(Fb[0]*rq0.x)*q0.x);  Fb[1] = rintf(rintf(Fb[1]*rq0.y)*q0.y);
                    Fb[2] = rintf(rintf(Fb[2]*rq0.z)*q0.z);  Fb[3] = rintf(rintf(Fb[3]*rq0.w)*q0.w);
                    Fb[4] = rintf(rintf(Fb[4]*rq1.x)*q1.x);  Fb[5] = rintf(rintf(Fb[5]*rq1.y)*q1.y);
                    Fb[6] = rintf(rintf(Fb[6]*rq1.z)*q1.z);  Fb[7] = rintf(rintf(Fb[7]*rq1.w)*q1.w);
                }
                #pragma unroll
                for (int l = 0; l < 8; l++) { Va[l] = 0.0f; Vb[l] = 0.0f; }
                #pragma unroll
                for (int k = 0; k < 8; k++) {
                    const float4 d0 = *(const float4*)&c_D[k*8];
                    const float4 d1 = *(const float4*)&c_D[k*8 + 4];
                    const float ta = Fa[k], tb = Fb[k];
                    Va[0] = fmaf(ta, d0.x, Va[0]);  Vb[0] = fmaf(tb, d0.x, Vb[0]);
                    Va[1] = fmaf(ta, d0.y, Va[1]);  Vb[1] = fmaf(tb, d0.y, Vb[1]);
                    Va[2] = fmaf(ta, d0.z, Va[2]);  Vb[2] = fmaf(tb, d0.z, Vb[2]);
                    Va[3] = fmaf(ta, d0.w, Va[3]);  Vb[3] = fmaf(tb, d0.w, Vb[3]);
                    Va[4] = fmaf(ta, d1.x, Va[4]);  Vb[4] = fmaf(tb, d1.x, Vb[4]);
                    Va[5] = fmaf(ta, d1.y, Va[5]);  Vb[5] = fmaf(tb, d1.y, Vb[5]);
                    Va[6] = fmaf(ta, d1.z, Va[6]);  Vb[6] = fmaf(tb, d1.z, Vb[6]);
                    Va[7] = fmaf(ta, d1.w, Va[7]);  Vb[7] = fmaf(tb, d1.w, Vb[7]);
                }
            }
            __syncwarp();   // all A' reads in unit done -> safe to overwrite
            *(float4*)(pW + ra*SAW)     = make_float4(Va[0], Va[1], Va[2], Va[3]);
            *(float4*)(pW + ra*SAW + 4) = make_float4(Va[4], Va[5], Va[6], Va[7]);
            *(float4*)(pW + rb*SAW)     = make_float4(Vb[0], Vb[1], Vb[2], Vb[3]);
            *(float4*)(pW + rb*SAW + 4) = make_float4(Vb[4], Vb[5], Vb[6], Vb[7]);
            __syncwarp();   // V visible within unit

            // ---- stage 3: Z = D^T * V (transpose) ----
            float zA[8], zB[8];
            #pragma unroll
            for (int l = 0; l < 8; l++) { zA[l] = 0.0f; zB[l] = 0.0f; }
            #pragma unroll
            for (int j = 0; j < 8; j++) {
                const float da = s_dt[ra][j];
                const float db = s_dt[rb][j];
                const float4 v0 = *(const float4*)(pW + j*SAW);
                const float4 v1 = *(const float4*)(pW + j*SAW + 4);
                zA[0] = fmaf(da, v0.x, zA[0]);  zB[0] = fmaf(db, v0.x, zB[0]);
                zA[1] = fmaf(da, v0.y, zA[1]);  zB[1] = fmaf(db, v0.y, zB[1]);
                zA[2] = fmaf(da, v0.z, zA[2]);  zB[2] = fmaf(db, v0.z, zB[2]);
                zA[3] = fmaf(da, v0.w, zA[3]);  zB[3] = fmaf(db, v0.w, zB[3]);
                zA[4] = fmaf(da, v1.x, zA[4]);  zB[4] = fmaf(db, v1.x, zB[4]);
                zA[5] = fmaf(da, v1.y, zA[5]);  zB[5] = fmaf(db, v1.y, zB[5]);
                zA[6] = fmaf(da, v1.z, zA[6]);  zB[6] = fmaf(db, v1.z, zB[6]);
                zA[7] = fmaf(da, v1.w, zA[7]);  zB[7] = fmaf(db, v1.w, zB[7]);
            }
            const float off = (c == 0) ? 128.0f : 0.0f;
            #pragma unroll
            for (int l = 0; l < 8; l++) { zA[l] += off; zB[l] += off; }
            __syncwarp();   // all V reads in unit done -> safe to overwrite
            *(float4*)(pW + ra*SAW)     = make_float4(zA[0], zA[1], zA[2], zA[3]);
            *(float4*)(pW + ra*SAW + 4) = make_float4(zA[4], zA[5], zA[6], zA[7]);
            *(float4*)(pW + rb*SAW)     = make_float4(zB[0], zB[1], zB[2], zB[3]);
            *(float4*)(pW + rb*SAW + 4) = make_float4(zB[4], zB[5], zB[6], zB[7]);
        }
        __syncthreads();

        // ---- phase 5: YCbCr -> RGB, clip, round, store ----
        {
            const float4 yv  = *(const float4*)&s_a[0][sy][px];
            const float4 cbv = *(const float4*)&s_a[1][sy][px];
            const float4 crv = *(const float4*)&s_a[2][sy][px];

            #define FIN(v) (rintf(fminf(fmaxf((v), 0.0f), 255.0f)) * (1.0f/255.0f))
            float4 R, G, Bv;
            R.x = FIN(fmaf(1.402f, crv.x, yv.x));  R.y = FIN(fmaf(1.402f, crv.y, yv.y));
            R.z = FIN(fmaf(1.402f, crv.z, yv.z));  R.w = FIN(fmaf(1.402f, crv.w, yv.w));
            G.x = FIN(fmaf(-0.714136286f, crv.x, fmaf(-0.344136286f, cbv.x, yv.x)));
            G.y = FIN(fmaf(-0.714136286f, crv.y, fmaf(-0.344136286f, cbv.y, yv.y)));
            G.z = FIN(fmaf(-0.714136286f, crv.z, fmaf(-0.344136286f, cbv.z, yv.z)));
            G.w = FIN(fmaf(-0.714136286f, crv.w, fmaf(-0.344136286f, cbv.w, yv.w)));
            Bv.x = FIN(fmaf(1.772f, cbv.x, yv.x)); Bv.y = FIN(fmaf(1.772f, cbv.y, yv.y));
            Bv.z = FIN(fmaf(1.772f, cbv.z, yv.z)); Bv.w = FIN(fmaf(1.772f, cbv.w, yv.w));

            const size_t oidx = (size_t)(ty0 + sy) * WIMG + (tx0 + px);
            *(float4*)&obase[oidx]           = R;
            *(float4*)&obase[plane + oidx]   = G;
            *(float4*)&obase[2*plane + oidx] = Bv;
        }
    }
}

extern "C" void kernel_launch(void* const* d_in, const int* in_sizes, int n_in,
                              void* d_out, int out_size)
{
    const float* x = nullptr;
    const float* q = nullptr;
    const float* d = nullptr;
    int nimg = 0;
    for (int i = 0; i < n_in; i++) {
        if (in_sizes[i] == 192)      q = (const float*)d_in[i];
        else if (in_sizes[i] == 64)  d = (const float*)d_in[i];
        else { x = (const float*)d_in[i]; nimg = in_sizes[i] / (3 * HIMG * WIMG); }
    }
    cudaMemcpyToSymbolAsync(c_D, d, 64 * sizeof(float), 0,
                            cudaMemcpyDeviceToDevice, 0);
    dim3 grid(WIMG / (TW * NTILE), HIMG / TH, nimg);
    jpeg_kernel<<<grid, NT>>>(x, q, d, (float*)d_out);
}

// round 16
// speedup vs baseline: 1.0247x; 1.0247x over previous
#include <cuda_runtime.h>

#define TH 16
#define TW 64
#define NT 256
#define HIMG 512
#define WIMG 512
#define SAW 68   // padded row stride for s_a
#define SCW 36   // padded row stride for s_c (half-res chroma)

__constant__ float c_D[64];   // DCT matrix, row-major
__device__ float g_q[192];    // precomputed quant table
__device__ float g_rq[192];   // precomputed 1/q

__global__ void table_kernel(const float* __restrict__ quant)
{
    const int i = threadIdx.x;   // 0..191
    float qv = rintf(quant[i] * 255.0f);
    float q1 = rintf((qv * 50.0f + 50.0f) / 100.0f);
    float q  = fminf(fmaxf(q1, 1.0f), 255.0f);
    g_q[i]  = q;
    g_rq[i] = 1.0f / q;
}

__global__ __launch_bounds__(NT, 5) void jpeg_kernel(
    const float* __restrict__ in, const float* __restrict__ quant,
    const float* __restrict__ dct, float* __restrict__ out)
{
    __shared__ __align__(16) float s_a[3][TH][SAW];   // y / A' / V / Z
    __shared__ __align__(16) float s_c[2][TH/2][SCW]; // half-res chroma
    __shared__ __align__(16) float s_d[8][8];         // D (lane-varying reads)
    __shared__ __align__(16) float s_dt[8][8];        // D^T
    __shared__ __align__(16) float s_e[8][4];         // E
    __shared__ __align__(16) float s_q[3][8][8];
    __shared__ __align__(16) float s_rq[3][8][8];

    const int tid = threadIdx.x;
    const int b   = blockIdx.z;
    const int ty0 = blockIdx.y * TH;
    const int tx0 = blockIdx.x * TW;

    const size_t plane = (size_t)HIMG * WIMG;
    const float* base  = in  + (size_t)b * 3 * plane;
    float*       obase = out + (size_t)b * 3 * plane;

    // ---- phase-1 global loads issued FIRST (overlap table setup with DRAM) ----
    const int sy = tid >> 4;                 // 0..15 (row)
    const int sx = tid & 15;                 // 0..15 (strip)
    const int px = sx * 4;
    const size_t gidx = (size_t)(ty0 + sy) * WIMG + (tx0 + px);
    const float4 r4 = __ldg((const float4*)&base[gidx]);
    const float4 g4 = __ldg((const float4*)&base[plane + gidx]);
    const float4 b4 = __ldg((const float4*)&base[2*plane + gidx]);

    // ---- tables (precomputed q; all loads overlap the DRAM loads above) ----
    if (tid < 64) {
        float v = dct[tid];
        int i = tid >> 3, j = tid & 7;
        s_d[i][j]  = v;
        s_dt[j][i] = v;
    }
    if (tid < 32) {
        int i = tid >> 2, h = tid & 3;
        s_e[i][h] = dct[i * 8 + 2 * h] + dct[i * 8 + 2 * h + 1];
    }
    if (tid >= 64) {
        int i = tid - 64;
        int ci = i >> 6, ri = (i >> 3) & 7, li = i & 7;
        s_q[ci][ri][li]  = __ldg(&g_q[i]);
        s_rq[ci][ri][li] = __ldg(&g_rq[i]);
    }

    // ---- phase 1: color transform; chroma 2x2 mean via in-warp shuffle ----
    {
        float R[4] = {255.0f*r4.x, 255.0f*r4.y, 255.0f*r4.z, 255.0f*r4.w};
        float G[4] = {255.0f*g4.x, 255.0f*g4.y, 255.0f*g4.z, 255.0f*g4.w};
        float B[4] = {255.0f*b4.x, 255.0f*b4.y, 255.0f*b4.z, 255.0f*b4.w};

        #define YV(R_,G_,B_)  fmaf(0.114f,(B_), fmaf(0.587f,(G_), 0.299f*(R_)))
        #define CBV(R_,G_,B_) (fmaf(0.5f,(B_),  fmaf(-0.331264108f,(G_), -0.168735892f*(R_))) + 128.0f)
        #define CRV(R_,G_,B_) (fmaf(-0.081312411f,(B_), fmaf(-0.418687589f,(G_), 0.5f*(R_))) + 128.0f)
        #define CL(v) fminf(fmaxf((v), 0.0f), 255.0f)

        float Y[4], CB[4], CR[4];
        #pragma unroll
        for (int e = 0; e < 4; e++) {
            Y[e]  = CL(YV(R[e], G[e], B[e])) - 128.0f;
            CB[e] = CL(CBV(R[e], G[e], B[e]));
            CR[e] = CL(CRV(R[e], G[e], B[e]));
        }
        *(float4*)&s_a[0][sy][px] = make_float4(Y[0], Y[1], Y[2], Y[3]);

        float pcb0 = __shfl_xor_sync(0xffffffffu, CB[0], 16);
        float pcb1 = __shfl_xor_sync(0xffffffffu, CB[1], 16);
        float pcb2 = __shfl_xor_sync(0xffffffffu, CB[2], 16);
        float pcb3 = __shfl_xor_sync(0xffffffffu, CB[3], 16);
        float pcr0 = __shfl_xor_sync(0xffffffffu, CR[0], 16);
        float pcr1 = __shfl_xor_sync(0xffffffffu, CR[1], 16);
        float pcr2 = __shfl_xor_sync(0xffffffffu, CR[2], 16);
        float pcr3 = __shfl_xor_sync(0xffffffffu, CR[3], 16);
        if ((sy & 1) == 0) {
            float cbm0 = 0.25f * (((CB[0] + CB[1]) + pcb0) + pcb1) - 128.0f;
            float cbm1 = 0.25f * (((CB[2] + CB[3]) + pcb2) + pcb3) - 128.0f;
            float crm0 = 0.25f * (((CR[0] + CR[1]) + pcr0) + pcr1) - 128.0f;
            float crm1 = 0.25f * (((CR[2] + CR[3]) + pcr2) + pcr3) - 128.0f;
            *(float2*)&s_c[0][sy >> 1][sx*2] = make_float2(cbm0, cbm1);
            *(float2*)&s_c[1][sy >> 1][sx*2] = make_float2(crm0, crm1);
        }
    }
    __syncthreads();

    // ---- assignment: 48 units * 4 threads (rows r and r+4); unit = warp-quad ----
    const bool act = tid < 192;
    const int unit = tid >> 2;    // 0..47
    const int r    = tid & 3;
    int c, by, bx;
    if (unit < 16) { c = 0; by = unit >> 3; bx = unit & 7; }
    else { int t = unit - 16; c = 1 + (t >> 4); int rem = t & 15; by = rem >> 3; bx = rem & 7; }
    const int ra = r, rb = r + 4;
    float* pW = &s_a[c][by*8][bx*8];

    if (act) {
        // ---- stage 1: A' = X * D^T (row-local; uniform const coeffs) ----
        if (c == 0) {
            #pragma unroll
            for (int pass = 0; pass < 2; pass++) {
                const int rr = pass ? rb : ra;
                const float4 x0 = *(const float4*)(pW + rr*SAW);
                const float4 x1 = *(const float4*)(pW + rr*SAW + 4);
                float A[8];
                #pragma unroll
                for (int l = 0; l < 8; l++) {
                    const float4 d0 = *(const float4*)&c_D[l*8];
                    const float4 d1 = *(const float4*)&c_D[l*8 + 4];
                    A[l] = fmaf(x1.w, d1.w, fmaf(x1.z, d1.z, fmaf(x1.y, d1.y,
                           fmaf(x1.x, d1.x, fmaf(x0.w, d0.w, fmaf(x0.z, d0.z,
                           fmaf(x0.y, d0.y, x0.x * d0.x)))))));
                }
                *(float4*)(pW + rr*SAW)     = make_float4(A[0], A[1], A[2], A[3]);
                *(float4*)(pW + rr*SAW + 4) = make_float4(A[4], A[5], A[6], A[7]);
            }
        } else {
            const float* pC = &s_c[c-1][by*4][bx*4];
            const float4 xh = *(const float4*)(pC + r*SCW);
            float A[8];
            #pragma unroll
            for (int l = 0; l < 8; l++) {
                const float4 d0 = *(const float4*)&c_D[l*8];
                const float4 d1 = *(const float4*)&c_D[l*8 + 4];
                float e0 = d0.x + d0.y, e1 = d0.z + d0.w;
                float e2 = d1.x + d1.y, e3 = d1.z + d1.w;
                A[l] = fmaf(xh.w, e3, fmaf(xh.z, e2, fmaf(xh.y, e1, xh.x * e0)));
            }
            *(float4*)(pW + r*SAW)     = make_float4(A[0], A[1], A[2], A[3]);
            *(float4*)(pW + r*SAW + 4) = make_float4(A[4], A[5], A[6], A[7]);
        }
        __syncwarp();   // unit (4 threads) is warp-local: A' visible

        // ---- stage 2: F = D * A' (transpose), quant/dequant, V = dec * D ----
        float Va[8], Vb[8];
        {
            float Fa[8], Fb[8];
            #pragma unroll
            for (int l = 0; l < 8; l++) { Fa[l] = 0.0f; Fb[l] = 0.0f; }
            if (c == 0) {
                #pragma unroll
                for (int j = 0; j < 8; j++) {
                    const float da = s_d[ra][j];
                    const float db = s_d[rb][j];
                    const float4 a0 = *(const float4*)(pW + j*SAW);
                    const float4 a1 = *(const float4*)(pW + j*SAW + 4);
                    Fa[0] = fmaf(da, a0.x, Fa[0]);  Fb[0] = fmaf(db, a0.x, Fb[0]);
                    Fa[1] = fmaf(da, a0.y, Fa[1]);  Fb[1] = fmaf(db, a0.y, Fb[1]);
                    Fa[2] = fmaf(da, a0.z, Fa[2]);  Fb[2] = fmaf(db, a0.z, Fb[2]);
                    Fa[3] = fmaf(da, a0.w, Fa[3]);  Fb[3] = fmaf(db, a0.w, Fb[3]);
                    Fa[4] = fmaf(da, a1.x, Fa[4]);  Fb[4] = fmaf(db, a1.x, Fb[4]);
                    Fa[5] = fmaf(da, a1.y, Fa[5]);  Fb[5] = fmaf(db, a1.y, Fb[5]);
                    Fa[6] = fmaf(da, a1.z, Fa[6]);  Fb[6] = fmaf(db, a1.z, Fb[6]);
                    Fa[7] = fmaf(da, a1.w, Fa[7]);  Fb[7] = fmaf(db, a1.w, Fb[7]);
                }
            } else {
                #pragma unroll
                for (int m = 0; m < 4; m++) {
                    const float ea = s_e[ra][m];
                    const float eb = s_e[rb][m];
                    const float4 a0 = *(const float4*)(pW + m*SAW);
                    const float4 a1 = *(const float4*)(pW + m*SAW + 4);
                    Fa[0] = fmaf(ea, a0.x, Fa[0]);  Fb[0] = fmaf(eb, a0.x, Fb[0]);
                    Fa[1] = fmaf(ea, a0.y, Fa[1]);  Fb[1] = fmaf(eb, a0.y, Fb[1]);
                    Fa[2] = fmaf(ea, a0.z, Fa[2]);  Fb[2] = fmaf(eb, a0.z, Fb[2]);
                    Fa[3] = fmaf(ea, a0.w, Fa[3]);  Fb[3] = fmaf(eb, a0.w, Fb[3]);
                    Fa[4] = fmaf(ea, a1.x, Fa[4]);  Fb[4] = fmaf(eb, a1.x, Fb[4]);
                    Fa[5] = fmaf(ea, a1.y, Fa[5]);  Fb[5] = fmaf(eb, a1.y, Fb[5]);
                    Fa[6] = fmaf(ea, a1.z, Fa[6]);  Fb[6] = fmaf(eb, a1.z, Fb[6]);
                    Fa[7] = fmaf(ea, a1.w, Fa[7]);  Fb[7] = fmaf(eb, a1.w, Fb[7]);
                }
            }
            {
                const float4 q0  = *(const float4*)&s_q[c][ra][0];
                const float4 q1  = *(const float4*)&s_q[c][ra][4];
                const float4 rq0 = *(const float4*)&s_rq[c][ra][0];
                const float4 rq1 = *(const float4*)&s_rq[c][ra][4];
                Fa[0] = rintf(rintf(Fa[0]*rq0.x)*q0.x);  Fa[1] = rintf(rintf(Fa[1]*rq0.y)*q0.y);
                Fa[2] = rintf(rintf(Fa[2]*rq0.z)*q0.z);  Fa[3] = rintf(rintf(Fa[3]*rq0.w)*q0.w);
                Fa[4] = rintf(rintf(Fa[4]*rq1.x)*q1.x);  Fa[5] = rintf(rintf(Fa[5]*rq1.y)*q1.y);
                Fa[6] = rintf(rintf(Fa[6]*rq1.z)*q1.z);  Fa[7] = rintf(rintf(Fa[7]*rq1.w)*q1.w);
            }
            {
                const float4 q0  = *(const float4*)&s_q[c][rb][0];
                const float4 q1  = *(const float4*)&s_q[c][rb][4];
                const float4 rq0 = *(const float4*)&s_rq[c][rb][0];
                const float4 rq1 = *(const float4*)&s_rq[c][rb][4];
                Fb[0] = rintf(rintf(Fb[0]*rq0.x)*q0.x);  Fb[1] = rintf(rintf(Fb[1]*rq0.y)*q0.y);
                Fb[2] = rintf(rintf(Fb[2]*rq0.z)*q0.z);  Fb[3] = rintf(rintf(Fb[3]*rq0.w)*q0.w);
                Fb[4] = rintf(rintf(Fb[4]*rq1.x)*q1.x);  Fb[5] = rintf(rintf(Fb[5]*rq1.y)*q1.y);
                Fb[6] = rintf(rintf(Fb[6]*rq1.z)*q1.z);  Fb[7] = rintf(rintf(Fb[7]*rq1.w)*q1.w);
            }
            #pragma unroll
            for (int l = 0; l < 8; l++) { Va[l] = 0.0f; Vb[l] = 0.0f; }
            #pragma unroll
            for (int k = 0; k < 8; k++) {
                const float4 d0 = *(const float4*)&c_D[k*8];
                const float4 d1 = *(const float4*)&c_D[k*8 + 4];
                const float ta = Fa[k], tb = Fb[k];
                Va[0] = fmaf(ta, d0.x, Va[0]);  Vb[0] = fmaf(tb, d0.x, Vb[0]);
                Va[1] = fmaf(ta, d0.y, Va[1]);  Vb[1] = fmaf(tb, d0.y, Vb[1]);
                Va[2] = fmaf(ta, d0.z, Va[2]);  Vb[2] = fmaf(tb, d0.z, Vb[2]);
                Va[3] = fmaf(ta, d0.w, Va[3]);  Vb[3] = fmaf(tb, d0.w, Vb[3]);
                Va[4] = fmaf(ta, d1.x, Va[4]);  Vb[4] = fmaf(tb, d1.x, Vb[4]);
                Va[5] = fmaf(ta, d1.y, Va[5]);  Vb[5] = fmaf(tb, d1.y, Vb[5]);
                Va[6] = fmaf(ta, d1.z, Va[6]);  Vb[6] = fmaf(tb, d1.z, Vb[6]);
                Va[7] = fmaf(ta, d1.w, Va[7]);  Vb[7] = fmaf(tb, d1.w, Vb[7]);
            }
        }
        __syncwarp();   // all A' reads in unit done -> safe to overwrite
        *(float4*)(pW + ra*SAW)     = make_float4(Va[0], Va[1], Va[2], Va[3]);
        *(float4*)(pW + ra*SAW + 4) = make_float4(Va[4], Va[5], Va[6], Va[7]);
        *(float4*)(pW + rb*SAW)     = make_float4(Vb[0], Vb[1], Vb[2], Vb[3]);
        *(float4*)(pW + rb*SAW + 4) = make_float4(Vb[4], Vb[5], Vb[6], Vb[7]);
        __syncwarp();   // V visible within unit

        // ---- stage 3: Z = D^T * V (transpose) ----
        float zA[8], zB[8];
        #pragma unroll
        for (int l = 0; l < 8; l++) { zA[l] = 0.0f; zB[l] = 0.0f; }
        #pragma unroll
        for (int j = 0; j < 8; j++) {
            const float da = s_dt[ra][j];
            const float db = s_dt[rb][j];
            const float4 v0 = *(const float4*)(pW + j*SAW);
            const float4 v1 = *(const float4*)(pW + j*SAW + 4);
            zA[0] = fmaf(da, v0.x, zA[0]);  zB[0] = fmaf(db, v0.x, zB[0]);
            zA[1] = fmaf(da, v0.y, zA[1]);  zB[1] = fmaf(db, v0.y, zB[1]);
            zA[2] = fmaf(da, v0.z, zA[2]);  zB[2] = fmaf(db, v0.z, zB[2]);
            zA[3] = fmaf(da, v0.w, zA[3]);  zB[3] = fmaf(db, v0.w, zB[3]);
            zA[4] = fmaf(da, v1.x, zA[4]);  zB[4] = fmaf(db, v1.x, zB[4]);
            zA[5] = fmaf(da, v1.y, zA[5]);  zB[5] = fmaf(db, v1.y, zB[5]);
            zA[6] = fmaf(da, v1.z, zA[6]);  zB[6] = fmaf(db, v1.z, zB[6]);
            zA[7] = fmaf(da, v1.w, zA[7]);  zB[7] = fmaf(db, v1.w, zB[7]);
        }
        const float off = (c == 0) ? 128.0f : 0.0f;
        #pragma unroll
        for (int l = 0; l < 8; l++) { zA[l] += off; zB[l] += off; }
        __syncwarp();   // all V reads in unit done -> safe to overwrite
        *(float4*)(pW + ra*SAW)     = make_float4(zA[0], zA[1], zA[2], zA[3]);
        *(float4*)(pW + ra*SAW + 4) = make_float4(zA[4], zA[5], zA[6], zA[7]);
        *(float4*)(pW + rb*SAW)     = make_float4(zB[0], zB[1], zB[2], zB[3]);
        *(float4*)(pW + rb*SAW + 4) = make_float4(zB[4], zB[5], zB[6], zB[7]);
    }
    __syncthreads();

    // ---- phase 5: YCbCr -> RGB, clip, round, store ----
    {
        const int py  = tid >> 4;
        const int px4 = (tid & 15) * 4;
        const float4 yv  = *(const float4*)&s_a[0][py][px4];
        const float4 cbv = *(const float4*)&s_a[1][py][px4];
        const float4 crv = *(const float4*)&s_a[2][py][px4];

        #define FIN(v) (rintf(fminf(fmaxf((v), 0.0f), 255.0f)) * (1.0f/255.0f))
        float4 R, G, Bv;
        R.x = FIN(fmaf(1.402f, crv.x, yv.x));  R.y = FIN(fmaf(1.402f, crv.y, yv.y));
        R.z = FIN(fmaf(1.402f, crv.z, yv.z));  R.w = FIN(fmaf(1.402f, crv.w, yv.w));
        G.x = FIN(fmaf(-0.714136286f, crv.x, fmaf(-0.344136286f, cbv.x, yv.x)));
        G.y = FIN(fmaf(-0.714136286f, crv.y, fmaf(-0.344136286f, cbv.y, yv.y)));
        G.z = FIN(fmaf(-0.714136286f, crv.z, fmaf(-0.344136286f, cbv.z, yv.z)));
        G.w = FIN(fmaf(-0.714136286f, crv.w, fmaf(-0.344136286f, cbv.w, yv.w)));
        Bv.x = FIN(fmaf(1.772f, cbv.x, yv.x)); Bv.y = FIN(fmaf(1.772f, cbv.y, yv.y));
        Bv.z = FIN(fmaf(1.772f, cbv.z, yv.z)); Bv.w = FIN(fmaf(1.772f, cbv.w, yv.w));

        const size_t idx = (size_t)(ty0 + py) * WIMG + (tx0 + px4);
        *(float4*)&obase[idx]           = R;
        *(float4*)&obase[plane + idx]   = G;
        *(float4*)&obase[2*plane + idx] = Bv;
    }
}

extern "C" void kernel_launch(void* const* d_in, const int* in_sizes, int n_in,
                              void* d_out, int out_size)
{
    const float* x = nullptr;
    const float* q = nullptr;
    const float* d = nullptr;
    int nimg = 0;
    for (int i = 0; i < n_in; i++) {
        if (in_sizes[i] == 192)      q = (const float*)d_in[i];
        else if (in_sizes[i] == 64)  d = (const float*)d_in[i];
        else { x = (const float*)d_in[i]; nimg = in_sizes[i] / (3 * HIMG * WIMG); }
    }
    cudaMemcpyToSymbolAsync(c_D, d, 64 * sizeof(float), 0,
                            cudaMemcpyDeviceToDevice, 0);
    table_kernel<<<1, 192>>>(q);
    dim3 grid(WIMG / TW, HIMG / TH, nimg);
    jpeg_kernel<<<grid, NT>>>(x, q, d, (float*)d_out);
}

// round 17
// speedup vs baseline: 1.0277x; 1.0029x over previous
#include <cuda_runtime.h>

#define TH 16
#define TW 64
#define NT 256
#define HIMG 512
#define WIMG 512
#define SAW 68   // padded row stride for s_a
#define SCW 36   // padded row stride for s_c (half-res chroma)

__constant__ float c_D[64];   // DCT matrix, row-major

__global__ __launch_bounds__(NT, 5) void jpeg_kernel(
    const float* __restrict__ in, const float* __restrict__ quant,
    const float* __restrict__ dct, float* __restrict__ out)
{
    __shared__ __align__(16) float s_a[3][TH][SAW];   // y / A' / V / Z
    __shared__ __align__(16) float s_c[2][TH/2][SCW]; // half-res chroma
    __shared__ __align__(16) float s_d[8][8];         // D (lane-varying reads)
    __shared__ __align__(16) float s_dt[8][8];        // D^T
    __shared__ __align__(16) float s_e[8][4];         // E
    __shared__ __align__(16) float s_q[3][8][8];
    __shared__ __align__(16) float s_rq[3][8][8];

    const int tid = threadIdx.x;
    const int b   = blockIdx.z;
    const int ty0 = blockIdx.y * TH;
    const int tx0 = blockIdx.x * TW;

    const size_t plane = (size_t)HIMG * WIMG;
    const float* base  = in  + (size_t)b * 3 * plane;
    float*       obase = out + (size_t)b * 3 * plane;

    // ---- phase-1 global loads issued FIRST (overlap table setup with DRAM) ----
    const int sy = tid >> 4;                 // 0..15 (row)
    const int sx = tid & 15;                 // 0..15 (strip)
    const int px = sx * 4;
    const size_t gidx = (size_t)(ty0 + sy) * WIMG + (tx0 + px);
    const float4 r4 = __ldg((const float4*)&base[gidx]);
    const float4 g4 = __ldg((const float4*)&base[plane + gidx]);
    const float4 b4 = __ldg((const float4*)&base[2*plane + gidx]);

    // ---- tables (overlapped with load latency; FDIV-free) ----
    if (tid < 64) {
        float v = dct[tid];
        int i = tid >> 3, j = tid & 7;
        s_d[i][j]  = v;
        s_dt[j][i] = v;
    }
    if (tid < 32) {
        int i = tid >> 2, h = tid & 3;
        s_e[i][h] = dct[i * 8 + 2 * h] + dct[i * 8 + 2 * h + 1];
    }
    if (tid >= 64) {
        int i = tid - 64;
        float qv = rintf(quant[i] * 255.0f);
        // (qv*50+50)/100 == (qv+1)/2 exactly in fp32 (integer halving is exact),
        // so this fmaf is bit-identical to the reference's division.
        float q1 = rintf(fmaf(qv, 0.5f, 0.5f));
        float q  = fminf(fmaxf(q1, 1.0f), 255.0f);
        int ci = i >> 6, ri = (i >> 3) & 7, li = i & 7;
        s_q[ci][ri][li]  = q;
        s_rq[ci][ri][li] = __fdividef(1.0f, q);   // <=1ulp rcp; used only inside rintf(acc*rq)
    }

    // ---- phase 1: color transform; chroma 2x2 mean via in-warp shuffle ----
    {
        float R[4] = {255.0f*r4.x, 255.0f*r4.y, 255.0f*r4.z, 255.0f*r4.w};
        float G[4] = {255.0f*g4.x, 255.0f*g4.y, 255.0f*g4.z, 255.0f*g4.w};
        float B[4] = {255.0f*b4.x, 255.0f*b4.y, 255.0f*b4.z, 255.0f*b4.w};

        #define YV(R_,G_,B_)  fmaf(0.114f,(B_), fmaf(0.587f,(G_), 0.299f*(R_)))
        #define CBV(R_,G_,B_) (fmaf(0.5f,(B_),  fmaf(-0.331264108f,(G_), -0.168735892f*(R_))) + 128.0f)
        #define CRV(R_,G_,B_) (fmaf(-0.081312411f,(B_), fmaf(-0.418687589f,(G_), 0.5f*(R_))) + 128.0f)
        #define CL(v) fminf(fmaxf((v), 0.0f), 255.0f)

        float Y[4], CB[4], CR[4];
        #pragma unroll
        for (int e = 0; e < 4; e++) {
            Y[e]  = CL(YV(R[e], G[e], B[e])) - 128.0f;
            CB[e] = CL(CBV(R[e], G[e], B[e]));
            CR[e] = CL(CRV(R[e], G[e], B[e]));
        }
        *(float4*)&s_a[0][sy][px] = make_float4(Y[0], Y[1], Y[2], Y[3]);

        float pcb0 = __shfl_xor_sync(0xffffffffu, CB[0], 16);
        float pcb1 = __shfl_xor_sync(0xffffffffu, CB[1], 16);
        float pcb2 = __shfl_xor_sync(0xffffffffu, CB[2], 16);
        float pcb3 = __shfl_xor_sync(0xffffffffu, CB[3], 16);
        float pcr0 = __shfl_xor_sync(0xffffffffu, CR[0], 16);
        float pcr1 = __shfl_xor_sync(0xffffffffu, CR[1], 16);
        float pcr2 = __shfl_xor_sync(0xffffffffu, CR[2], 16);
        float pcr3 = __shfl_xor_sync(0xffffffffu, CR[3], 16);
        if ((sy & 1) == 0) {
            float cbm0 = 0.25f * (((CB[0] + CB[1]) + pcb0) + pcb1) - 128.0f;
            float cbm1 = 0.25f * (((CB[2] + CB[3]) + pcb2) + pcb3) - 128.0f;
            float crm0 = 0.25f * (((CR[0] + CR[1]) + pcr0) + pcr1) - 128.0f;
            float crm1 = 0.25f * (((CR[2] + CR[3]) + pcr2) + pcr3) - 128.0f;
            *(float2*)&s_c[0][sy >> 1][sx*2] = make_float2(cbm0, cbm1);
            *(float2*)&s_c[1][sy >> 1][sx*2] = make_float2(crm0, crm1);
        }
    }
    __syncthreads();

    // ---- assignment: 48 units * 4 threads (rows r and r+4); unit = warp-quad ----
    const bool act = tid < 192;
    const int unit = tid >> 2;    // 0..47
    const int r    = tid & 3;
    int c, by, bx;
    if (unit < 16) { c = 0; by = unit >> 3; bx = unit & 7; }
    else { int t = unit - 16; c = 1 + (t >> 4); int rem = t & 15; by = rem >> 3; bx = rem & 7; }
    const int ra = r, rb = r + 4;
    float* pW = &s_a[c][by*8][bx*8];

    if (act) {
        // ---- stage 1: A' = X * D^T (row-local; uniform const coeffs) ----
        if (c == 0) {
            #pragma unroll
            for (int pass = 0; pass < 2; pass++) {
                const int rr = pass ? rb : ra;
                const float4 x0 = *(const float4*)(pW + rr*SAW);
                const float4 x1 = *(const float4*)(pW + rr*SAW + 4);
                float A[8];
                #pragma unroll
                for (int l = 0; l < 8; l++) {
                    const float4 d0 = *(const float4*)&c_D[l*8];
                    const float4 d1 = *(const float4*)&c_D[l*8 + 4];
                    A[l] = fmaf(x1.w, d1.w, fmaf(x1.z, d1.z, fmaf(x1.y, d1.y,
                           fmaf(x1.x, d1.x, fmaf(x0.w, d0.w, fmaf(x0.z, d0.z,
                           fmaf(x0.y, d0.y, x0.x * d0.x)))))));
                }
                *(float4*)(pW + rr*SAW)     = make_float4(A[0], A[1], A[2], A[3]);
                *(float4*)(pW + rr*SAW + 4) = make_float4(A[4], A[5], A[6], A[7]);
            }
        } else {
            const float* pC = &s_c[c-1][by*4][bx*4];
            const float4 xh = *(const float4*)(pC + r*SCW);
            float A[8];
            #pragma unroll
            for (int l = 0; l < 8; l++) {
                const float4 d0 = *(const float4*)&c_D[l*8];
                const float4 d1 = *(const float4*)&c_D[l*8 + 4];
                float e0 = d0.x + d0.y, e1 = d0.z + d0.w;
                float e2 = d1.x + d1.y, e3 = d1.z + d1.w;
                A[l] = fmaf(xh.w, e3, fmaf(xh.z, e2, fmaf(xh.y, e1, xh.x * e0)));
            }
            *(float4*)(pW + r*SAW)     = make_float4(A[0], A[1], A[2], A[3]);
            *(float4*)(pW + r*SAW + 4) = make_float4(A[4], A[5], A[6], A[7]);
        }
        __syncwarp();   // unit (4 threads) is warp-local: A' visible

        // ---- stage 2: F = D * A' (transpose), quant/dequant, V = dec * D ----
        float Va[8], Vb[8];
        {
            float Fa[8], Fb[8];
            #pragma unroll
            for (int l = 0; l < 8; l++) { Fa[l] = 0.0f; Fb[l] = 0.0f; }
            if (c == 0) {
                #pragma unroll
                for (int j = 0; j < 8; j++) {
                    const float da = s_d[ra][j];
                    const float db = s_d[rb][j];
                    const float4 a0 = *(const float4*)(pW + j*SAW);
                    const float4 a1 = *(const float4*)(pW + j*SAW + 4);
                    Fa[0] = fmaf(da, a0.x, Fa[0]);  Fb[0] = fmaf(db, a0.x, Fb[0]);
                    Fa[1] = fmaf(da, a0.y, Fa[1]);  Fb[1] = fmaf(db, a0.y, Fb[1]);
                    Fa[2] = fmaf(da, a0.z, Fa[2]);  Fb[2] = fmaf(db, a0.z, Fb[2]);
                    Fa[3] = fmaf(da, a0.w, Fa[3]);  Fb[3] = fmaf(db, a0.w, Fb[3]);
                    Fa[4] = fmaf(da, a1.x, Fa[4]);  Fb[4] = fmaf(db, a1.x, Fb[4]);
                    Fa[5] = fmaf(da, a1.y, Fa[5]);  Fb[5] = fmaf(db, a1.y, Fb[5]);
                    Fa[6] = fmaf(da, a1.z, Fa[6]);  Fb[6] = fmaf(db, a1.z, Fb[6]);
                    Fa[7] = fmaf(da, a1.w, Fa[7]);  Fb[7] = fmaf(db, a1.w, Fb[7]);
                }
            } else {
                #pragma unroll
                for (int m = 0; m < 4; m++) {
                    const float ea = s_e[ra][m];
                    const float eb = s_e[rb][m];
                    const float4 a0 = *(const float4*)(pW + m*SAW);
                    const float4 a1 = *(const float4*)(pW + m*SAW + 4);
                    Fa[0] = fmaf(ea, a0.x, Fa[0]);  Fb[0] = fmaf(eb, a0.x, Fb[0]);
                    Fa[1] = fmaf(ea, a0.y, Fa[1]);  Fb[1] = fmaf(eb, a0.y, Fb[1]);
                    Fa[2] = fmaf(ea, a0.z, Fa[2]);  Fb[2] = fmaf(eb, a0.z, Fb[2]);
                    Fa[3] = fmaf(ea, a0.w, Fa[3]);  Fb[3] = fmaf(eb, a0.w, Fb[3]);
                    Fa[4] = fmaf(ea, a1.x, Fa[4]);  Fb[4] = fmaf(eb, a1.x, Fb[4]);
                    Fa[5] = fmaf(ea, a1.y, Fa[5]);  Fb[5] = fmaf(eb, a1.y, Fb[5]);
                    Fa[6] = fmaf(ea, a1.z, Fa[6]);  Fb[6] = fmaf(eb, a1.z, Fb[6]);
                    Fa[7] = fmaf(ea, a1.w, Fa[7]);  Fb[7] = fmaf(eb, a1.w, Fb[7]);
                }
            }
            {
                const float4 q0  = *(const float4*)&s_q[c][ra][0];
                const float4 q1  = *(const float4*)&s_q[c][ra][4];
                const float4 rq0 = *(const float4*)&s_rq[c][ra][0];
                const float4 rq1 = *(const float4*)&s_rq[c][ra][4];
                Fa[0] = rintf(rintf(Fa[0]*rq0.x)*q0.x);  Fa[1] = rintf(rintf(Fa[1]*rq0.y)*q0.y);
                Fa[2] = rintf(rintf(Fa[2]*rq0.z)*q0.z);  Fa[3] = rintf(rintf(Fa[3]*rq0.w)*q0.w);
                Fa[4] = rintf(rintf(Fa[4]*rq1.x)*q1.x);  Fa[5] = rintf(rintf(Fa[5]*rq1.y)*q1.y);
                Fa[6] = rintf(rintf(Fa[6]*rq1.z)*q1.z);  Fa[7] = rintf(rintf(Fa[7]*rq1.w)*q1.w);
            }
            {
                const float4 q0  = *(const float4*)&s_q[c][rb][0];
                const float4 q1  = *(const float4*)&s_q[c][rb][4];
                const float4 rq0 = *(const float4*)&s_rq[c][rb][0];
                const float4 rq1 = *(const float4*)&s_rq[c][rb][4];
                Fb[0] = rintf(rintf(Fb[0]*rq0.x)*q0.x);  Fb[1] = rintf(rintf(Fb[1]*rq0.y)*q0.y);
                Fb[2] = rintf(rintf(Fb[2]*rq0.z)*q0.z);  Fb[3] = rintf(rintf(Fb[3]*rq0.w)*q0.w);
                Fb[4] = rintf(rintf(Fb[4]*rq1.x)*q1.x);  Fb[5] = rintf(rintf(Fb[5]*rq1.y)*q1.y);
                Fb[6] = rintf(rintf(Fb[6]*rq1.z)*q1.z);  Fb[7] = rintf(rintf(Fb[7]*rq1.w)*q1.w);
            }
            #pragma unroll
            for (int l = 0; l < 8; l++) { Va[l] = 0.0f; Vb[l] = 0.0f; }
            #pragma unroll
            for (int k = 0; k < 8; k++) {
                const float4 d0 = *(const float4*)&c_D[k*8];
                const float4 d1 = *(const float4*)&c_D[k*8 + 4];
                const float ta = Fa[k], tb = Fb[k];
                Va[0] = fmaf(ta, d0.x, Va[0]);  Vb[0] = fmaf(tb, d0.x, Vb[0]);
                Va[1] = fmaf(ta, d0.y, Va[1]);  Vb[1] = fmaf(tb, d0.y, Vb[1]);
                Va[2] = fmaf(ta, d0.z, Va[2]);  Vb[2] = fmaf(tb, d0.z, Vb[2]);
                Va[3] = fmaf(ta, d0.w, Va[3]);  Vb[3] = fmaf(tb, d0.w, Vb[3]);
                Va[4] = fmaf(ta, d1.x, Va[4]);  Vb[4] = fmaf(tb, d1.x, Vb[4]);
                Va[5] = fmaf(ta, d1.y, Va[5]);  Vb[5] = fmaf(tb, d1.y, Vb[5]);
                Va[6] = fmaf(ta, d1.z, Va[6]);  Vb[6] = fmaf(tb, d1.z, Vb[6]);
                Va[7] = fmaf(ta, d1.w, Va[7]);  Vb[7] = fmaf(tb, d1.w, Vb[7]);
            }
        }
        __syncwarp();   // all A' reads in unit done -> safe to overwrite
        *(float4*)(pW + ra*SAW)     = make_float4(Va[0], Va[1], Va[2], Va[3]);
        *(float4*)(pW + ra*SAW + 4) = make_float4(Va[4], Va[5], Va[6], Va[7]);
        *(float4*)(pW + rb*SAW)     = make_float4(Vb[0], Vb[1], Vb[2], Vb[3]);
        *(float4*)(pW + rb*SAW + 4) = make_float4(Vb[4], Vb[5], Vb[6], Vb[7]);
        __syncwarp();   // V visible within unit

        // ---- stage 3: Z = D^T * V (transpose) ----
        float zA[8], zB[8];
        #pragma unroll
        for (int l = 0; l < 8; l++) { zA[l] = 0.0f; zB[l] = 0.0f; }
        #pragma unroll
        for (int j = 0; j < 8; j++) {
            const float da = s_dt[ra][j];
            const float db = s_dt[rb][j];
            const float4 v0 = *(const float4*)(pW + j*SAW);
            const float4 v1 = *(const float4*)(pW + j*SAW + 4);
            zA[0] = fmaf(da, v0.x, zA[0]);  zB[0] = fmaf(db, v0.x, zB[0]);
            zA[1] = fmaf(da, v0.y, zA[1]);  zB[1] = fmaf(db, v0.y, zB[1]);
            zA[2] = fmaf(da, v0.z, zA[2]);  zB[2] = fmaf(db, v0.z, zB[2]);
            zA[3] = fmaf(da, v0.w, zA[3]);  zB[3] = fmaf(db, v0.w, zB[3]);
            zA[4] = fmaf(da, v1.x, zA[4]);  zB[4] = fmaf(db, v1.x, zB[4]);
            zA[5] = fmaf(da, v1.y, zA[5]);  zB[5] = fmaf(db, v1.y, zB[5]);
            zA[6] = fmaf(da, v1.z, zA[6]);  zB[6] = fmaf(db, v1.z, zB[6]);
            zA[7] = fmaf(da, v1.w, zA[7]);  zB[7] = fmaf(db, v1.w, zB[7]);
        }
        const float off = (c == 0) ? 128.0f : 0.0f;
        #pragma unroll
        for (int l = 0; l < 8; l++) { zA[l] += off; zB[l] += off; }
        __syncwarp();   // all V reads in unit done -> safe to overwrite
        *(float4*)(pW + ra*SAW)     = make_float4(zA[0], zA[1], zA[2], zA[3]);
        *(float4*)(pW + ra*SAW + 4) = make_float4(zA[4], zA[5], zA[6], zA[7]);
        *(float4*)(pW + rb*SAW)     = make_float4(zB[0], zB[1], zB[2], zB[3]);
        *(float4*)(pW + rb*SAW + 4) = make_float4(zB[4], zB[5], zB[6], zB[7]);
    }
    __syncthreads();

    // ---- phase 5: YCbCr -> RGB, clip, round, store ----
    {
        const int py  = tid >> 4;
        const int px4 = (tid & 15) * 4;
        const float4 yv  = *(const float4*)&s_a[0][py][px4];
        const float4 cbv = *(const float4*)&s_a[1][py][px4];
        const float4 crv = *(const float4*)&s_a[2][py][px4];

        #define FIN(v) (rintf(fminf(fmaxf((v), 0.0f), 255.0f)) * (1.0f/255.0f))
        float4 R, G, Bv;
        R.x = FIN(fmaf(1.402f, crv.x, yv.x));  R.y = FIN(fmaf(1.402f, crv.y, yv.y));
        R.z = FIN(fmaf(1.402f, crv.z, yv.z));  R.w = FIN(fmaf(1.402f, crv.w, yv.w));
        G.x = FIN(fmaf(-0.714136286f, crv.x, fmaf(-0.344136286f, cbv.x, yv.x)));
        G.y = FIN(fmaf(-0.714136286f, crv.y, fmaf(-0.344136286f, cbv.y, yv.y)));
        G.z = FIN(fmaf(-0.714136286f, crv.z, fmaf(-0.344136286f, cbv.z, yv.z)));
        G.w = FIN(fmaf(-0.714136286f, crv.w, fmaf(-0.344136286f, cbv.w, yv.w)));
        Bv.x = FIN(fmaf(1.772f, cbv.x, yv.x)); Bv.y = FIN(fmaf(1.772f, cbv.y, yv.y));
        Bv.z = FIN(fmaf(1.772f, cbv.z, yv.z)); Bv.w = FIN(fmaf(1.772f, cbv.w, yv.w));

        const size_t idx = (size_t)(ty0 + py) * WIMG + (tx0 + px4);
        *(float4*)&obase[idx]           = R;
        *(float4*)&obase[plane + idx]   = G;
        *(float4*)&obase[2*plane + idx] = Bv;
    }
}

extern "C" void kernel_launch(void* const* d_in, const int* in_sizes, int n_in,
                              void* d_out, int out_size)
{
    const float* x = nullptr;
    const float* q = nullptr;
    const float* d = nullptr;
    int nimg = 0;
    for (int i = 0; i < n_in; i++) {
        if (in_sizes[i] == 192)      q = (const float*)d_in[i];
        else if (in_sizes[i] == 64)  d = (const float*)d_in[i];
        else { x = (const float*)d_in[i]; nimg = in_sizes[i] / (3 * HIMG * WIMG); }
    }
    cudaMemcpyToSymbolAsync(c_D, d, 64 * sizeof(float), 0,
                            cudaMemcpyDeviceToDevice, 0);
    dim3 grid(WIMG / TW, HIMG / TH, nimg);
    jpeg_kernel<<<grid, NT>>>(x, q, d, (float*)d_out);
}